// round 14
// baseline (speedup 1.0000x reference)
#include <cuda_runtime.h>
#include <cuda_fp16.h>
#include <cstdint>

#define IN_DIM  128
#define OUT_DIM 128
#define NHEADS  4
#define NEG_SLOPE 0.2f

#define N_MAX 50000
#define E_MAX 1600000
#define FULL 0xFFFFFFFFu
#define HIST_BLOCKS 296   // ~25% of resident CTA slots; LTS-atomic-bound anyway

// -------- device scratch (static: no allocation allowed) --------
__device__ float  g_hq   [N_MAX * NHEADS];
__device__ float  g_kact [N_MAX * NHEADS];
__device__ float  g_qagg [N_MAX * NHEADS];
__device__ __half g_hproj[(size_t)N_MAX * OUT_DIM];
__device__ int    g_cnt  [N_MAX];   // zeroed at load; re-zeroed inside scan1 each run
__device__ int    g_off  [N_MAX + 1];
__device__ int    g_pos  [N_MAX];
__device__ int    g_bsum [256];
__device__ int    g_csr_col[E_MAX];

// ===== fused front kernel: hist (low bids, grid-stride) + projections =====
#define NPB 16
__global__ __launch_bounds__(128) void proj_hist_kernel(
    const float* __restrict__ x,
    const float* __restrict__ Wq, const float* __restrict__ Wk,
    const float* __restrict__ Wl, const float* __restrict__ bl,
    const int* __restrict__ rows, int N, int E)
{
    const int t = threadIdx.x;

    if ((int)blockIdx.x < HIST_BLOCKS) {
        // ---------- histogram partition ----------
        int i = blockIdx.x * 128 + t;
        const int stride = HIST_BLOCKS * 128;
        for (; i < E; i += stride)
            atomicAdd(&g_cnt[__ldg(rows + i)], 1);
        return;
    }

    // ---------- projection partition ----------
    __shared__ float xs[NPB * IN_DIM];
    const int base = ((int)blockIdx.x - HIST_BLOCKS) * NPB;
    const int nn = min(NPB, N - base);
    if (nn <= 0) return;

    {
        const float4* xg = (const float4*)(x + (size_t)base * IN_DIM);
        float4* xs4 = (float4*)xs;
        const int tot4 = nn * (IN_DIM / 4);
        for (int i = t; i < tot4; i += 128) xs4[i] = xg[i];
    }
    __syncthreads();

    // per-head q/k projections: t = n2*8 + h
    {
        const int n2 = t >> 3;
        const int h  = t & 7;
        if (n2 < nn) {
            const float* wrow = (h < 4) ? (Wq + h * IN_DIM) : (Wk + (h - 4) * IN_DIM);
            const float4* w4 = (const float4*)wrow;
            const float4* xr = (const float4*)(xs + n2 * IN_DIM);
            float d = 0.0f;
            #pragma unroll
            for (int k = 0; k < IN_DIM / 4; k++) {
                float4 w = w4[k]; float4 xv = xr[k];
                d += w.x * xv.x + w.y * xv.y + w.z * xv.z + w.w * xv.w;
            }
            const int node = base + n2;
            if (h < 4) g_hq[node * NHEADS + h] = d;
            else       g_kact[node * NHEADS + (h - 4)] = (d >= 0.0f) ? d : NEG_SLOPE * d;
        }
    }

    float acc[NPB];
    #pragma unroll
    for (int n = 0; n < NPB; n++) acc[n] = 0.0f;

    const float4* wl4 = (const float4*)(Wl + (size_t)t * IN_DIM);
    #pragma unroll 4
    for (int k = 0; k < IN_DIM / 4; k++) {
        float4 w = wl4[k];
        #pragma unroll
        for (int n = 0; n < NPB; n++) {
            float4 xv = ((const float4*)(xs + n * IN_DIM))[k];
            acc[n] += w.x * xv.x + w.y * xv.y + w.z * xv.z + w.w * xv.w;
        }
    }
    const float b = bl[t];
    for (int n = 0; n < nn; n++)
        g_hproj[(size_t)(base + n) * OUT_DIM + t] = __float2half_rn(acc[n] + b);
}

// ================= scan (2 stages) =================
__device__ __forceinline__ int warp_incl_scan(int v, int lane) {
    #pragma unroll
    for (int d = 1; d < 32; d <<= 1) {
        int t = __shfl_up_sync(FULL, v, d);
        if (lane >= d) v += t;
    }
    return v;
}

__global__ __launch_bounds__(256) void scan1_kernel(int N) {
    int i = blockIdx.x * 256 + threadIdx.x;
    int lane = threadIdx.x & 31, wid = threadIdx.x >> 5;
    int v = 0;
    if (i < N) { v = g_cnt[i]; g_cnt[i] = 0; }  // re-zero for next replay
    int s = warp_incl_scan(v, lane);
    __shared__ int wsum[8];
    if (lane == 31) wsum[wid] = s;
    __syncthreads();
    if (wid == 0) {
        int ws = (lane < 8) ? wsum[lane] : 0;
        #pragma unroll
        for (int d = 1; d < 8; d <<= 1) {
            int t = __shfl_up_sync(FULL, ws, d);
            if (lane >= d) ws += t;
        }
        if (lane < 8) wsum[lane] = ws;
    }
    __syncthreads();
    int excl = s - v + (wid > 0 ? wsum[wid - 1] : 0);
    if (i < N) g_off[i] = excl;
    if (threadIdx.x == 255) g_bsum[blockIdx.x] = excl + v;   // raw block total
}

// fused scan2+scan3: each block computes its own prefix over the raw block
// totals (warp 0: strided partial sums + warp reduce), then finalizes offsets.
__global__ __launch_bounds__(256) void scan23_kernel(int N, int E, int nb) {
    __shared__ int blk_prefix;
    const int tid = threadIdx.x;
    const int bid = blockIdx.x;
    if (tid < 32) {
        int partial = 0;
        for (int j = tid; j < bid; j += 32) partial += g_bsum[j];
        #pragma unroll
        for (int d = 16; d; d >>= 1) partial += __shfl_xor_sync(FULL, partial, d);
        if (tid == 0) blk_prefix = partial;
    }
    __syncthreads();
    int i = bid * 256 + tid;
    if (i < N) {
        int o = g_off[i] + blk_prefix;
        g_off[i] = o;
        g_pos[i] = o;
    }
    if (i == 0) g_off[N] = E;
}

// ================= kernel: scatter edges into CSR =================
__global__ __launch_bounds__(256) void scatter_kernel(
    const int* __restrict__ rows, const int* __restrict__ cols, int E)
{
    int e = blockIdx.x * 256 + threadIdx.x;
    if (e >= E) return;
    int r = rows[e];
    int p = atomicAdd(&g_pos[r], 1);
    g_csr_col[p] = cols[e];
}

// ================= kernel: q_agg via CSR (no atomics) =================
__global__ __launch_bounds__(256) void qagg_csr_kernel(int N) {
    int w = (blockIdx.x * 256 + threadIdx.x) >> 5;
    int lane = threadIdx.x & 31;
    if (w >= N) return;
    int beg = g_off[w], end = g_off[w + 1];
    float4 acc = {0.f, 0.f, 0.f, 0.f};
    for (int e = beg + lane; e < end; e += 32) {
        int c = __ldg(g_csr_col + e);
        float4 v = __ldg(((const float4*)g_hq) + c);
        acc.x += v.x; acc.y += v.y; acc.z += v.z; acc.w += v.w;
    }
    #pragma unroll
    for (int d = 16; d; d >>= 1) {
        acc.x += __shfl_xor_sync(FULL, acc.x, d);
        acc.y += __shfl_xor_sync(FULL, acc.y, d);
        acc.z += __shfl_xor_sync(FULL, acc.z, d);
        acc.w += __shfl_xor_sync(FULL, acc.w, d);
    }
    if (lane == 0) ((float4*)g_qagg)[w] = acc;
}

// ================= fused attention + aggregation (warp per node) ======
// identical structure to R13; ONLY the value gather is fp16 (half bytes)
__device__ __forceinline__ void agg_strip(float4& acc, float a, int c, int lane, int cnt) {
    const uint2* hp = (const uint2*)g_hproj;
    #pragma unroll 8
    for (int j = 0; j < 32; j++) {
        if (j >= cnt) break;
        float aj = __shfl_sync(FULL, a, j);
        int   cj = __shfl_sync(FULL, c, j);
        uint2 u = __ldg(hp + (size_t)cj * (OUT_DIM / 4) + lane);
        float2 f0 = __half22float2(*reinterpret_cast<const __half2*>(&u.x));
        float2 f1 = __half22float2(*reinterpret_cast<const __half2*>(&u.y));
        acc.x = fmaf(aj, f0.x, acc.x);
        acc.y = fmaf(aj, f0.y, acc.y);
        acc.z = fmaf(aj, f1.x, acc.z);
        acc.w = fmaf(aj, f1.y, acc.w);
    }
}

__global__ __launch_bounds__(256) void attn_agg_kernel(float* __restrict__ out, int N) {
    int node = (blockIdx.x * 256 + threadIdx.x) >> 5;
    int lane = threadIdx.x & 31;
    if (node >= N) return;
    const int beg = g_off[node], end = g_off[node + 1];
    const int deg = end - beg;

    float4* outp = ((float4*)out) + (size_t)node * (OUT_DIM / 4) + lane;
    if (deg == 0) { float4 z = {0.f,0.f,0.f,0.f}; *outp = z; return; }

    const float4 ka = ((const float4*)g_kact)[node];
    float4 acc = {0.f, 0.f, 0.f, 0.f};

    // pass 1: per-head max
    float4 mx = {-3.4e38f, -3.4e38f, -3.4e38f, -3.4e38f};
    for (int e = beg + lane; e < end; e += 32) {
        int c = __ldg(g_csr_col + e);
        float4 q = __ldg(((const float4*)g_qagg) + c);
        mx.x = fmaxf(mx.x, ka.x * q.x);
        mx.y = fmaxf(mx.y, ka.y * q.y);
        mx.z = fmaxf(mx.z, ka.z * q.z);
        mx.w = fmaxf(mx.w, ka.w * q.w);
    }
    #pragma unroll
    for (int d = 16; d; d >>= 1) {
        mx.x = fmaxf(mx.x, __shfl_xor_sync(FULL, mx.x, d));
        mx.y = fmaxf(mx.y, __shfl_xor_sync(FULL, mx.y, d));
        mx.z = fmaxf(mx.z, __shfl_xor_sync(FULL, mx.z, d));
        mx.w = fmaxf(mx.w, __shfl_xor_sync(FULL, mx.w, d));
    }

    // pass 2: per-head sum of exp
    float4 sm = {0.f, 0.f, 0.f, 0.f};
    for (int e = beg + lane; e < end; e += 32) {
        int c = __ldg(g_csr_col + e);
        float4 q = __ldg(((const float4*)g_qagg) + c);
        sm.x += __expf(ka.x * q.x - mx.x);
        sm.y += __expf(ka.y * q.y - mx.y);
        sm.z += __expf(ka.z * q.z - mx.z);
        sm.w += __expf(ka.w * q.w - mx.w);
    }
    #pragma unroll
    for (int d = 16; d; d >>= 1) {
        sm.x += __shfl_xor_sync(FULL, sm.x, d);
        sm.y += __shfl_xor_sync(FULL, sm.y, d);
        sm.z += __shfl_xor_sync(FULL, sm.z, d);
        sm.w += __shfl_xor_sync(FULL, sm.w, d);
    }
    float4 inv;
    inv.x = 0.25f * __fdividef(1.0f, sm.x + 1e-8f);
    inv.y = 0.25f * __fdividef(1.0f, sm.y + 1e-8f);
    inv.z = 0.25f * __fdividef(1.0f, sm.z + 1e-8f);
    inv.w = 0.25f * __fdividef(1.0f, sm.w + 1e-8f);

    // pass 3: alpha per edge strip, broadcast + accumulate
    for (int base = beg; base < end; base += 32) {
        int e = base + lane;
        float a = 0.0f; int c = 0;
        if (e < end) {
            c = __ldg(g_csr_col + e);
            float4 q = __ldg(((const float4*)g_qagg) + c);
            a = __expf(ka.x * q.x - mx.x) * inv.x
              + __expf(ka.y * q.y - mx.y) * inv.y
              + __expf(ka.z * q.z - mx.z) * inv.z
              + __expf(ka.w * q.w - mx.w) * inv.w;
        }
        agg_strip(acc, a, c, lane, min(32, end - base));
    }

    // fused final leaky relu + single coalesced write
    acc.x = (acc.x >= 0.f) ? acc.x : NEG_SLOPE * acc.x;
    acc.y = (acc.y >= 0.f) ? acc.y : NEG_SLOPE * acc.y;
    acc.z = (acc.z >= 0.f) ? acc.z : NEG_SLOPE * acc.z;
    acc.w = (acc.w >= 0.f) ? acc.w : NEG_SLOPE * acc.w;
    *outp = acc;
}

// ================= launch =================
extern "C" void kernel_launch(void* const* d_in, const int* in_sizes, int n_in,
                              void* d_out, int out_size)
{
    const float* x  = (const float*)d_in[0];
    const int*   ei = (const int*)d_in[1];
    const float* Wq = (const float*)d_in[2];
    const float* Wk = (const float*)d_in[3];
    const float* Wl = (const float*)d_in[4];
    const float* bl = (const float*)d_in[5];
    float* out = (float*)d_out;

    const int N = in_sizes[0] / IN_DIM;
    const int E = in_sizes[1] / 2;
    const int* rows = ei;
    const int* cols = ei + E;
    const int nblocksN = (N + 255) / 256;
    const int proj_blocks = (N + NPB - 1) / NPB;

    // 1: hist (resident low-bid partition) + projections, concurrent in one launch
    proj_hist_kernel<<<HIST_BLOCKS + proj_blocks, 128>>>(x, Wq, Wk, Wl, bl, rows, N, E);
    // 2-3: offsets (scan1 re-zeros g_cnt for next replay; scan23 fuses stages 2+3)
    scan1_kernel<<<nblocksN, 256>>>(N);
    scan23_kernel<<<nblocksN, 256>>>(N, E, nblocksN);
    // 4: scatter edges into CSR
    scatter_kernel<<<(E + 255) / 256, 256>>>(rows, cols, E);
    // 5: q aggregation (no atomics)
    qagg_csr_kernel<<<(N * 32 + 255) / 256, 256>>>(N);
    // 6: fused softmax + weighted aggregation + leaky
    attn_agg_kernel<<<(N * 32 + 255) / 256, 256>>>(out, N);
}

// round 15
// speedup vs baseline: 1.0005x; 1.0005x over previous
#include <cuda_runtime.h>
#include <cstdint>

#define IN_DIM  128
#define OUT_DIM 128
#define NHEADS  4
#define NEG_SLOPE 0.2f

#define N_MAX 50000
#define E_MAX 1600000
#define FULL 0xFFFFFFFFu
#define HIST_BLOCKS 296   // ~25% of resident CTA slots; LTS-atomic-bound anyway
#define QAGG_BLOCKS 400   // low-bid partition of the scatter launch
#define SCAT_BLOCKS 784   // high-bid partition: CSR scatter

// -------- device scratch (static: no allocation allowed) --------
__device__ float g_hq   [N_MAX * NHEADS];
__device__ float g_kact [N_MAX * NHEADS];
__device__ float g_qagg [N_MAX * NHEADS];
__device__ float g_hproj[(size_t)N_MAX * OUT_DIM];
__device__ int   g_cnt  [N_MAX];   // zeroed at load; re-zeroed inside scan1 each run
__device__ int   g_off  [N_MAX + 1];
__device__ int   g_pos  [N_MAX];
__device__ int   g_bsum [256];
__device__ int   g_csr_col[E_MAX];

__device__ __forceinline__ void red_add_v4(float* p, float a, float b, float c, float d) {
    asm volatile("red.global.add.v4.f32 [%0], {%1, %2, %3, %4};"
                 :: "l"(p), "f"(a), "f"(b), "f"(c), "f"(d) : "memory");
}

// ===== fused front kernel: hist (low bids, grid-stride) + projections =====
#define NPB 16
__global__ __launch_bounds__(128) void proj_hist_kernel(
    const float* __restrict__ x,
    const float* __restrict__ Wq, const float* __restrict__ Wk,
    const float* __restrict__ Wl, const float* __restrict__ bl,
    const int* __restrict__ rows, int N, int E)
{
    const int t = threadIdx.x;

    if ((int)blockIdx.x < HIST_BLOCKS) {
        // ---------- histogram partition ----------
        int i = blockIdx.x * 128 + t;
        const int stride = HIST_BLOCKS * 128;
        for (; i < E; i += stride)
            atomicAdd(&g_cnt[__ldg(rows + i)], 1);
        return;
    }

    // ---------- projection partition ----------
    __shared__ float xs[NPB * IN_DIM];
    const int base = ((int)blockIdx.x - HIST_BLOCKS) * NPB;
    const int nn = min(NPB, N - base);
    if (nn <= 0) return;

    {
        const float4* xg = (const float4*)(x + (size_t)base * IN_DIM);
        float4* xs4 = (float4*)xs;
        const int tot4 = nn * (IN_DIM / 4);
        for (int i = t; i < tot4; i += 128) xs4[i] = xg[i];
    }
    __syncthreads();

    // per-head q/k projections: t = n2*8 + h
    {
        const int n2 = t >> 3;
        const int h  = t & 7;
        if (n2 < nn) {
            const float* wrow = (h < 4) ? (Wq + h * IN_DIM) : (Wk + (h - 4) * IN_DIM);
            const float4* w4 = (const float4*)wrow;
            const float4* xr = (const float4*)(xs + n2 * IN_DIM);
            float d = 0.0f;
            #pragma unroll
            for (int k = 0; k < IN_DIM / 4; k++) {
                float4 w = w4[k]; float4 xv = xr[k];
                d += w.x * xv.x + w.y * xv.y + w.z * xv.z + w.w * xv.w;
            }
            const int node = base + n2;
            if (h < 4) g_hq[node * NHEADS + h] = d;
            else       g_kact[node * NHEADS + (h - 4)] = (d >= 0.0f) ? d : NEG_SLOPE * d;
        }
    }

    float acc[NPB];
    #pragma unroll
    for (int n = 0; n < NPB; n++) acc[n] = 0.0f;

    const float4* wl4 = (const float4*)(Wl + (size_t)t * IN_DIM);
    #pragma unroll 4
    for (int k = 0; k < IN_DIM / 4; k++) {
        float4 w = wl4[k];
        #pragma unroll
        for (int n = 0; n < NPB; n++) {
            float4 xv = ((const float4*)(xs + n * IN_DIM))[k];
            acc[n] += w.x * xv.x + w.y * xv.y + w.z * xv.z + w.w * xv.w;
        }
    }
    const float b = bl[t];
    for (int n = 0; n < nn; n++)
        g_hproj[(size_t)(base + n) * OUT_DIM + t] = acc[n] + b;
}

// ================= scan (2 stages) =================
__device__ __forceinline__ int warp_incl_scan(int v, int lane) {
    #pragma unroll
    for (int d = 1; d < 32; d <<= 1) {
        int t = __shfl_up_sync(FULL, v, d);
        if (lane >= d) v += t;
    }
    return v;
}

__global__ __launch_bounds__(256) void scan1_kernel(int N) {
    int i = blockIdx.x * 256 + threadIdx.x;
    int lane = threadIdx.x & 31, wid = threadIdx.x >> 5;
    int v = 0;
    if (i < N) { v = g_cnt[i]; g_cnt[i] = 0; }  // re-zero for next replay
    int s = warp_incl_scan(v, lane);
    __shared__ int wsum[8];
    if (lane == 31) wsum[wid] = s;
    __syncthreads();
    if (wid == 0) {
        int ws = (lane < 8) ? wsum[lane] : 0;
        #pragma unroll
        for (int d = 1; d < 8; d <<= 1) {
            int t = __shfl_up_sync(FULL, ws, d);
            if (lane >= d) ws += t;
        }
        if (lane < 8) wsum[lane] = ws;
    }
    __syncthreads();
    int excl = s - v + (wid > 0 ? wsum[wid - 1] : 0);
    if (i < N) g_off[i] = excl;
    if (threadIdx.x == 255) g_bsum[blockIdx.x] = excl + v;   // raw block total
}

// fused scan2+scan3: per-block prefix over raw block totals, finalize offsets,
// and zero g_qagg (needed by the atomic qagg partition in scatter_qagg_kernel).
__global__ __launch_bounds__(256) void scan23_kernel(int N, int E, int nb) {
    __shared__ int blk_prefix;
    const int tid = threadIdx.x;
    const int bid = blockIdx.x;
    if (tid < 32) {
        int partial = 0;
        for (int j = tid; j < bid; j += 32) partial += g_bsum[j];
        #pragma unroll
        for (int d = 16; d; d >>= 1) partial += __shfl_xor_sync(FULL, partial, d);
        if (tid == 0) blk_prefix = partial;
    }
    __syncthreads();
    int i = bid * 256 + tid;
    if (i < N) {
        int o = g_off[i] + blk_prefix;
        g_off[i] = o;
        g_pos[i] = o;
        ((float4*)g_qagg)[i] = make_float4(0.f, 0.f, 0.f, 0.f);
    }
    if (i == 0) g_off[N] = E;
}

// ===== fused: qagg-from-COO (low bids) + CSR scatter (high bids), one wave ====
__global__ __launch_bounds__(256) void scatter_qagg_kernel(
    const int* __restrict__ rows, const int* __restrict__ cols, int E)
{
    const int t = threadIdx.x;
    if ((int)blockIdx.x < QAGG_BLOCKS) {
        // ---------- qagg partition: q_agg[row] += h_q[col] ----------
        int i = blockIdx.x * 256 + t;
        const int stride = QAGG_BLOCKS * 256;
        for (; i < E; i += stride) {
            int r = __ldg(rows + i);
            int c = __ldg(cols + i);
            float4 v = __ldg(((const float4*)g_hq) + c);
            red_add_v4(g_qagg + (size_t)r * 4, v.x, v.y, v.z, v.w);
        }
        return;
    }
    // ---------- scatter partition ----------
    int i = ((int)blockIdx.x - QAGG_BLOCKS) * 256 + t;
    const int stride = SCAT_BLOCKS * 256;
    for (; i < E; i += stride) {
        int r = __ldg(rows + i);
        int p = atomicAdd(&g_pos[r], 1);
        g_csr_col[p] = __ldg(cols + i);
    }
}

// ================= fused attention + aggregation (warp per node) ======
__device__ __forceinline__ void agg_strip(float4& acc, float a, int c, int lane, int cnt) {
    #pragma unroll 8
    for (int j = 0; j < 32; j++) {
        if (j >= cnt) break;
        float aj = __shfl_sync(FULL, a, j);
        int   cj = __shfl_sync(FULL, c, j);
        float4 v = __ldg(((const float4*)g_hproj) + (size_t)cj * (OUT_DIM / 4) + lane);
        acc.x = fmaf(aj, v.x, acc.x);
        acc.y = fmaf(aj, v.y, acc.y);
        acc.z = fmaf(aj, v.z, acc.z);
        acc.w = fmaf(aj, v.w, acc.w);
    }
}

__global__ __launch_bounds__(256) void attn_agg_kernel(float* __restrict__ out, int N) {
    int node = (blockIdx.x * 256 + threadIdx.x) >> 5;
    int lane = threadIdx.x & 31;
    if (node >= N) return;
    const int beg = g_off[node], end = g_off[node + 1];
    const int deg = end - beg;

    float4* outp = ((float4*)out) + (size_t)node * (OUT_DIM / 4) + lane;
    if (deg == 0) { float4 z = {0.f,0.f,0.f,0.f}; *outp = z; return; }

    const float4 ka = ((const float4*)g_kact)[node];
    float4 acc = {0.f, 0.f, 0.f, 0.f};

    // pass 1: per-head max
    float4 mx = {-3.4e38f, -3.4e38f, -3.4e38f, -3.4e38f};
    for (int e = beg + lane; e < end; e += 32) {
        int c = __ldg(g_csr_col + e);
        float4 q = __ldg(((const float4*)g_qagg) + c);
        mx.x = fmaxf(mx.x, ka.x * q.x);
        mx.y = fmaxf(mx.y, ka.y * q.y);
        mx.z = fmaxf(mx.z, ka.z * q.z);
        mx.w = fmaxf(mx.w, ka.w * q.w);
    }
    #pragma unroll
    for (int d = 16; d; d >>= 1) {
        mx.x = fmaxf(mx.x, __shfl_xor_sync(FULL, mx.x, d));
        mx.y = fmaxf(mx.y, __shfl_xor_sync(FULL, mx.y, d));
        mx.z = fmaxf(mx.z, __shfl_xor_sync(FULL, mx.z, d));
        mx.w = fmaxf(mx.w, __shfl_xor_sync(FULL, mx.w, d));
    }

    // pass 2: per-head sum of exp
    float4 sm = {0.f, 0.f, 0.f, 0.f};
    for (int e = beg + lane; e < end; e += 32) {
        int c = __ldg(g_csr_col + e);
        float4 q = __ldg(((const float4*)g_qagg) + c);
        sm.x += __expf(ka.x * q.x - mx.x);
        sm.y += __expf(ka.y * q.y - mx.y);
        sm.z += __expf(ka.z * q.z - mx.z);
        sm.w += __expf(ka.w * q.w - mx.w);
    }
    #pragma unroll
    for (int d = 16; d; d >>= 1) {
        sm.x += __shfl_xor_sync(FULL, sm.x, d);
        sm.y += __shfl_xor_sync(FULL, sm.y, d);
        sm.z += __shfl_xor_sync(FULL, sm.z, d);
        sm.w += __shfl_xor_sync(FULL, sm.w, d);
    }
    float4 inv;
    inv.x = 0.25f * __fdividef(1.0f, sm.x + 1e-8f);
    inv.y = 0.25f * __fdividef(1.0f, sm.y + 1e-8f);
    inv.z = 0.25f * __fdividef(1.0f, sm.z + 1e-8f);
    inv.w = 0.25f * __fdividef(1.0f, sm.w + 1e-8f);

    // pass 3: alpha per edge strip, broadcast + accumulate
    for (int base = beg; base < end; base += 32) {
        int e = base + lane;
        float a = 0.0f; int c = 0;
        if (e < end) {
            c = __ldg(g_csr_col + e);
            float4 q = __ldg(((const float4*)g_qagg) + c);
            a = __expf(ka.x * q.x - mx.x) * inv.x
              + __expf(ka.y * q.y - mx.y) * inv.y
              + __expf(ka.z * q.z - mx.z) * inv.z
              + __expf(ka.w * q.w - mx.w) * inv.w;
        }
        agg_strip(acc, a, c, lane, min(32, end - base));
    }

    // fused final leaky relu + single coalesced write
    acc.x = (acc.x >= 0.f) ? acc.x : NEG_SLOPE * acc.x;
    acc.y = (acc.y >= 0.f) ? acc.y : NEG_SLOPE * acc.y;
    acc.z = (acc.z >= 0.f) ? acc.z : NEG_SLOPE * acc.z;
    acc.w = (acc.w >= 0.f) ? acc.w : NEG_SLOPE * acc.w;
    *outp = acc;
}

// ================= launch =================
extern "C" void kernel_launch(void* const* d_in, const int* in_sizes, int n_in,
                              void* d_out, int out_size)
{
    const float* x  = (const float*)d_in[0];
    const int*   ei = (const int*)d_in[1];
    const float* Wq = (const float*)d_in[2];
    const float* Wk = (const float*)d_in[3];
    const float* Wl = (const float*)d_in[4];
    const float* bl = (const float*)d_in[5];
    float* out = (float*)d_out;

    const int N = in_sizes[0] / IN_DIM;
    const int E = in_sizes[1] / 2;
    const int* rows = ei;
    const int* cols = ei + E;
    const int nblocksN = (N + 255) / 256;
    const int proj_blocks = (N + NPB - 1) / NPB;

    // 1: hist (resident low-bid partition) + projections, concurrent in one launch
    proj_hist_kernel<<<HIST_BLOCKS + proj_blocks, 128>>>(x, Wq, Wk, Wl, bl, rows, N, E);
    // 2-3: offsets (scan1 re-zeros g_cnt; scan23 finalizes offsets + zeros g_qagg)
    scan1_kernel<<<nblocksN, 256>>>(N);
    scan23_kernel<<<nblocksN, 256>>>(N, E, nblocksN);
    // 4: qagg-from-COO + CSR scatter, concurrent in one launch
    scatter_qagg_kernel<<<QAGG_BLOCKS + SCAT_BLOCKS, 256>>>(rows, cols, E);
    // 5: fused softmax + weighted aggregation + leaky
    attn_agg_kernel<<<(N * 32 + 255) / 256, 256>>>(out, N);
}